// round 17
// baseline (speedup 1.0000x reference)
#include <cuda_runtime.h>
#include <cuda_bf16.h>
#include <cstdint>

// ---------------------------------------------------------------------------
// MHA via tf32 mma.sync (m16n8k8) everywhere.
// x[4,2048,1024] -> QKV gemm -> 16-head flash attention -> proj gemm
// GEMM: CTA 128x256, 512 thr, warp tile 64x32, paired-k float2 SMEM (R15).
// Attention (new): Q/K/V pre-converted to tf32 bits at scatter; paired-k
// float2 SMEM for Q/K/V/P so every fragment gather is one LDS.64.
// ---------------------------------------------------------------------------

#define B_   4
#define T_   2048
#define D_   1024
#define H_   16
#define DK_  64
#define M_   (B_ * T_)          // 8192

// Scratch (allocation-free rule: __device__ globals)
__device__ uint32_t g_Q[B_ * H_ * T_ * DK_];   // tf32 bits, pre-scaled 1/8
__device__ uint32_t g_K[B_ * H_ * T_ * DK_];   // tf32 bits
__device__ uint32_t g_V[B_ * H_ * T_ * DK_];   // tf32 bits
__device__ float    g_O[B_ * T_ * D_];         // attention output, [B,T,D]

__device__ __forceinline__ uint32_t f2tf(float f) {
    uint32_t u; asm("cvt.rna.tf32.f32 %0, %1;" : "=r"(u) : "f"(f)); return u;
}

// D = A(16x8,row) * B(8x8,col) + D, tf32 in / f32 out
__device__ __forceinline__ void mma8(float c[4],
                                     uint32_t a0, uint32_t a1, uint32_t a2, uint32_t a3,
                                     uint32_t b0, uint32_t b1) {
    asm volatile("mma.sync.aligned.m16n8k8.row.col.f32.tf32.tf32.f32 "
                 "{%0,%1,%2,%3}, {%4,%5,%6,%7}, {%8,%9}, {%0,%1,%2,%3};"
                 : "+f"(c[0]), "+f"(c[1]), "+f"(c[2]), "+f"(c[3])
                 : "r"(a0), "r"(a1), "r"(a2), "r"(a3), "r"(b0), "r"(b1));
}

__device__ __forceinline__ void qkv_scatter(int m, int n, float c) {
    int b = m >> 11, t = m & 2047;
    int which = n >> 10, rem = n & 1023;
    int h = rem >> 6, dd = rem & 63;
    size_t idx = ((size_t)((b << 4) + h) * T_ + t) * DK_ + dd;
    if (which == 0)      g_Q[idx] = f2tf(c * 0.125f);   // 1/sqrt(64)
    else if (which == 1) g_K[idx] = f2tf(c);
    else                 g_V[idx] = f2tf(c);
}

// ---------------------------------------------------------------------------
// TN GEMM: C[M,N] = A[M,K] @ Bw[N,K]^T   (identical to passing R15 version)
// BM=128, BN=256, BK=16, 512 thr (16 warps, 2x8), warp tile 64x32.
// ---------------------------------------------------------------------------
#define GMP 132
#define GNP 260
#define GA_F2 (8 * GMP)                 // float2 per A buffer
#define GB_F2 (8 * GNP)
#define GEMM_SMEM_BYTES ((2 * GA_F2 + 2 * GB_F2) * 8)   // 50176

__device__ __forceinline__ void st_paired(float2* base, int pitch, int r, int c4,
                                          float4 v) {
    int pb = (c4 >> 3) * 4;
    int h  = (c4 & 4) ? 1 : 0;
    float* w = (float*)(base + (size_t)pb * pitch + r);
    w[h]             = __uint_as_float(f2tf(v.x));
    w[2 * pitch + h] = __uint_as_float(f2tf(v.y));
    w[4 * pitch + h] = __uint_as_float(f2tf(v.z));
    w[6 * pitch + h] = __uint_as_float(f2tf(v.w));
}

__global__ __launch_bounds__(512, 1)
void gemm_tf32_kernel(const float* __restrict__ A, const float* __restrict__ Bw,
                      float* __restrict__ out, int M, int N, int K, int mode)
{
    extern __shared__ float2 smf2[];
    float2* Af2 = smf2;                 // [2][8][GMP]
    float2* Bf2 = smf2 + 2 * GA_F2;     // [2][8][GNP]

    const float* __restrict__ Ap = (mode == 1) ? (const float*)g_O : A;

    const int m0 = blockIdx.y * 128, n0 = blockIdx.x * 256;
    const int tid = threadIdx.x;
    const int warp = tid >> 5, lane = tid & 31;
    const int wy = warp >> 3, wx = warp & 7;      // 2 x 8 warp grid
    const int qr = lane >> 2, qc = lane & 3;

    const int lr  = tid >> 2;                     // load row: 0..127
    const int lc4 = (tid & 3) * 4;                // load k-offset (0,4,8,12)

    float acc[4][4][4];
#pragma unroll
    for (int i = 0; i < 4; i++)
#pragma unroll
        for (int j = 0; j < 4; j++)
#pragma unroll
            for (int r = 0; r < 4; r++) acc[i][j][r] = 0.0f;

    // ---- prologue: load k-block 0 into buffer 0 ----
    {
        float4 av = *(const float4*)(Ap + (size_t)(m0 + lr) * K + lc4);
        st_paired(Af2, GMP, lr, lc4, av);
#pragma unroll
        for (int i = 0; i < 2; i++) {
            float4 bv = *(const float4*)(Bw + (size_t)(n0 + lr + i * 128) * K + lc4);
            st_paired(Bf2, GNP, lr + i * 128, lc4, bv);
        }
    }
    __syncthreads();

    for (int k0 = 0; k0 < K; k0 += 16) {
        const int buf = (k0 >> 4) & 1;
        const float2* Ab = Af2 + (size_t)buf * GA_F2;
        const float2* Bb = Bf2 + (size_t)buf * GB_F2;
        const bool more = (k0 + 16) < K;

        float4 pa, pb[2];
        if (more) {
            pa = *(const float4*)(Ap + (size_t)(m0 + lr) * K + k0 + 16 + lc4);
#pragma unroll
            for (int i = 0; i < 2; i++)
                pb[i] = *(const float4*)(Bw + (size_t)(n0 + lr + i * 128) * K + k0 + 16 + lc4);
        }

#pragma unroll
        for (int kk = 0; kk < 2; kk++) {
            const float2* apl = Ab + (size_t)(kk * 4 + qc) * GMP;
            const float2* bpl = Bb + (size_t)(kk * 4 + qc) * GNP;
            uint32_t afr[4][4];
#pragma unroll
            for (int i = 0; i < 4; i++) {
                int mr = wy * 64 + i * 16 + qr;
                float2 lo = apl[mr];
                float2 hi = apl[mr + 8];
                afr[i][0] = __float_as_uint(lo.x);
                afr[i][1] = __float_as_uint(hi.x);
                afr[i][2] = __float_as_uint(lo.y);
                afr[i][3] = __float_as_uint(hi.y);
            }
            uint32_t bfr[4][2];
#pragma unroll
            for (int j = 0; j < 4; j++) {
                float2 bv = bpl[wx * 32 + j * 8 + qr];
                bfr[j][0] = __float_as_uint(bv.x);
                bfr[j][1] = __float_as_uint(bv.y);
            }
#pragma unroll
            for (int i = 0; i < 4; i++)
#pragma unroll
                for (int j = 0; j < 4; j++)
                    mma8(acc[i][j], afr[i][0], afr[i][1], afr[i][2], afr[i][3],
                         bfr[j][0], bfr[j][1]);
        }

        if (more) {
            float2* An = Af2 + (size_t)(buf ^ 1) * GA_F2;
            float2* Bn = Bf2 + (size_t)(buf ^ 1) * GB_F2;
            st_paired(An, GMP, lr, lc4, pa);
#pragma unroll
            for (int i = 0; i < 2; i++)
                st_paired(Bn, GNP, lr + i * 128, lc4, pb[i]);
        }
        __syncthreads();
    }

    // ---- epilogue ----
#pragma unroll
    for (int i = 0; i < 4; i++) {
#pragma unroll
        for (int j = 0; j < 4; j++) {
            int mA = m0 + wy * 64 + i * 16 + qr;
            int nA = n0 + wx * 32 + j * 8 + qc * 2;
            if (mode == 0) {
                qkv_scatter(mA,     nA,     acc[i][j][0]);
                qkv_scatter(mA,     nA + 1, acc[i][j][1]);
                qkv_scatter(mA + 8, nA,     acc[i][j][2]);
                qkv_scatter(mA + 8, nA + 1, acc[i][j][3]);
            } else {
                *(float2*)(out + (size_t)mA * N + nA)
                    = make_float2(acc[i][j][0], acc[i][j][1]);
                *(float2*)(out + (size_t)(mA + 8) * N + nA)
                    = make_float2(acc[i][j][2], acc[i][j][3]);
            }
        }
    }
}

// ---------------------------------------------------------------------------
// Flash attention, tf32 mma, paired-k float2 SMEM.
// One block per (bh, 128-q-row tile). Bc=64. 8 warps; warp w owns q-rows
// 16w..16w+15.
// SMEM (float2): Qs[32 planes][QP] | Ks[32][KP] | Vs[32][KP] | Ps[32][QP]
//   Q/K/P paired over the contraction dim; V paired over key.
//   Plane p = kk*4+q holds {X[m][kb+q], X[m][kb+q+4]}, kb = kk*8.
// QP=132, KP=68: both ≡ 4 (mod 16) -> conflict-free LDS.64 gathers.
// ---------------------------------------------------------------------------
#define QP 132
#define KP 68
#define A_SMEM_BYTES ((32 * QP * 2 + 32 * KP * 2) * 8)   // 102400

// store 4 consecutive k-values (c4..c4+3) of row r, paired-k layout
__device__ __forceinline__ void st_pk(float2* base, int pitch, int r, int c4,
                                      uint4 v) {
    int pb = (c4 >> 3) * 4;
    int h  = (c4 & 4) ? 1 : 0;
    uint32_t* w = (uint32_t*)(base + (size_t)pb * pitch + r) + h;
    w[0]         = v.x;
    w[2 * pitch] = v.y;
    w[4 * pitch] = v.z;
    w[6 * pitch] = v.w;
}

// store 4 consecutive positions (c4..c4+3) of k-row r, paired over r
__device__ __forceinline__ void st_pr(float2* base, int pitch, int r, int c4,
                                      uint4 v) {
    int p = (r >> 3) * 4 + (r & 3);
    int h = (r & 4) ? 1 : 0;
    uint32_t* w = (uint32_t*)(base + (size_t)p * pitch + c4) + h;
    w[0] = v.x; w[2] = v.y; w[4] = v.z; w[6] = v.w;
}

__global__ __launch_bounds__(256, 2)
void attn_tf32_kernel()
{
    extern __shared__ float2 smf2[];
    float2* Qs = smf2;                       // 32 * QP
    float2* Ks = Qs + 32 * QP;               // 32 * KP
    float2* Vs = Ks + 32 * KP;               // 32 * KP
    float2* Ps = Vs + 32 * KP;               // 32 * QP

    const int qt = blockIdx.x;          // 0..15
    const int bh = blockIdx.y;          // 0..63
    const uint32_t* __restrict__ Qg = g_Q + (size_t)bh * (T_ * DK_) + (size_t)qt * (128 * DK_);
    const uint32_t* __restrict__ Kg = g_K + (size_t)bh * (T_ * DK_);
    const uint32_t* __restrict__ Vg = g_V + (size_t)bh * (T_ * DK_);

    const int tid = threadIdx.x, warp = tid >> 5, lane = tid & 31;
    const int qr = lane >> 2, qc = lane & 3;
    const int wrow = warp * 16;

    // Load Q tile (128x64 tf32 bits) into paired-k layout
#pragma unroll
    for (int i = 0; i < 8; i++) {
        int v = tid + i * 256, r = v >> 4, c4 = (v & 15) * 4;
        uint4 qv = *(const uint4*)(Qg + r * 64 + c4);
        st_pk(Qs, QP, r, c4, qv);
    }

    float o[8][4];
#pragma unroll
    for (int j = 0; j < 8; j++)
#pragma unroll
        for (int r = 0; r < 4; r++) o[j][r] = 0.0f;
    float m0r = -1e30f, m1r = -1e30f, l0 = 0.0f, l1 = 0.0f;

    for (int kt = 0; kt < T_ / 64; kt++) {
        __syncthreads();
#pragma unroll
        for (int i = 0; i < 4; i++) {
            int v = tid + i * 256, r = v >> 4, c4 = (v & 15) * 4;
            uint4 kv = *(const uint4*)(Kg + kt * 4096 + r * 64 + c4);
            st_pk(Ks, KP, r, c4, kv);              // paired over dim
            uint4 vv = *(const uint4*)(Vg + kt * 4096 + r * 64 + c4);
            st_pr(Vs, KP, r, c4, vv);              // paired over key
        }
        __syncthreads();

        // S[16 x 64] = Q @ K^T
        float s[8][4];
#pragma unroll
        for (int j = 0; j < 8; j++)
#pragma unroll
            for (int r = 0; r < 4; r++) s[j][r] = 0.0f;
#pragma unroll
        for (int kk = 0; kk < 8; kk++) {
            const float2* apl = Qs + (size_t)(kk * 4 + qc) * QP;
            float2 alo = apl[wrow + qr];
            float2 ahi = apl[wrow + qr + 8];
            uint32_t a0 = __float_as_uint(alo.x);
            uint32_t a1 = __float_as_uint(ahi.x);
            uint32_t a2 = __float_as_uint(alo.y);
            uint32_t a3 = __float_as_uint(ahi.y);
            const float2* bpl = Ks + (size_t)(kk * 4 + qc) * KP;
#pragma unroll
            for (int j = 0; j < 8; j++) {
                float2 bv = bpl[j * 8 + qr];
                mma8(s[j], a0, a1, a2, a3,
                     __float_as_uint(bv.x), __float_as_uint(bv.y));
            }
        }

        // Online softmax (rows wrow+qr and wrow+qr+8; quad-wide reduce)
        float v0 = -1e30f, v1 = -1e30f;
#pragma unroll
        for (int j = 0; j < 8; j++) {
            v0 = fmaxf(v0, fmaxf(s[j][0], s[j][1]));
            v1 = fmaxf(v1, fmaxf(s[j][2], s[j][3]));
        }
        v0 = fmaxf(v0, __shfl_xor_sync(0xffffffffu, v0, 1));
        v0 = fmaxf(v0, __shfl_xor_sync(0xffffffffu, v0, 2));
        v1 = fmaxf(v1, __shfl_xor_sync(0xffffffffu, v1, 1));
        v1 = fmaxf(v1, __shfl_xor_sync(0xffffffffu, v1, 2));
        float mn0 = fmaxf(m0r, v0), mn1 = fmaxf(m1r, v1);
        float al0 = __expf(m0r - mn0), al1 = __expf(m1r - mn1);
        m0r = mn0; m1r = mn1;

        float rs0 = 0.0f, rs1 = 0.0f;
#pragma unroll
        for (int j = 0; j < 8; j++) {
            float p0 = __expf(s[j][0] - mn0), p1 = __expf(s[j][1] - mn0);
            float p2 = __expf(s[j][2] - mn1), p3 = __expf(s[j][3] - mn1);
            rs0 += p0 + p1; rs1 += p2 + p3;
            // store P (paired over key): col c = j*8 + qc*2 + e
#pragma unroll
            for (int e = 0; e < 2; e++) {
                int c7 = qc * 2 + e;                       // 0..7 within k-group
                int plane = j * 4 + (c7 & 3);
                int h = (c7 & 4) ? 1 : 0;
                uint32_t* w = (uint32_t*)(Ps + (size_t)plane * QP) + h;
                w[2 * (wrow + qr)]     = f2tf(e ? p1 : p0);
                w[2 * (wrow + qr + 8)] = f2tf(e ? p3 : p2);
            }
            o[j][0] *= al0; o[j][1] *= al0; o[j][2] *= al1; o[j][3] *= al1;
        }
        rs0 += __shfl_xor_sync(0xffffffffu, rs0, 1);
        rs0 += __shfl_xor_sync(0xffffffffu, rs0, 2);
        rs1 += __shfl_xor_sync(0xffffffffu, rs1, 1);
        rs1 += __shfl_xor_sync(0xffffffffu, rs1, 2);
        l0 = l0 * al0 + rs0;
        l1 = l1 * al1 + rs1;
        __syncwarp();   // Ps rows owned+read by this warp only

        // O[16 x 64] += P @ V
#pragma unroll
        for (int kk = 0; kk < 8; kk++) {
            const float2* apl = Ps + (size_t)(kk * 4 + qc) * QP;
            float2 alo = apl[wrow + qr];
            float2 ahi = apl[wrow + qr + 8];
            uint32_t a0 = __float_as_uint(alo.x);
            uint32_t a1 = __float_as_uint(ahi.x);
            uint32_t a2 = __float_as_uint(alo.y);
            uint32_t a3 = __float_as_uint(ahi.y);
            const float2* bpl = Vs + (size_t)(kk * 4 + qc) * KP;
#pragma unroll
            for (int j = 0; j < 8; j++) {
                float2 bv = bpl[j * 8 + qr];
                mma8(o[j], a0, a1, a2, a3,
                     __float_as_uint(bv.x), __float_as_uint(bv.y));
            }
        }
    }

    // Normalize and store to g_O [B,T,D]
    const int b = bh >> 4, h = bh & 15;
    const float inv0 = 1.0f / l0, inv1 = 1.0f / l1;
    const int t0 = qt * 128 + wrow + qr;
#pragma unroll
    for (int j = 0; j < 8; j++) {
        int dcol = h * 64 + j * 8 + qc * 2;
        *(float2*)&g_O[((size_t)(b * T_ + t0)) * D_ + dcol]
            = make_float2(o[j][0] * inv0, o[j][1] * inv0);
        *(float2*)&g_O[((size_t)(b * T_ + t0 + 8)) * D_ + dcol]
            = make_float2(o[j][2] * inv1, o[j][3] * inv1);
    }
}

// ---------------------------------------------------------------------------
extern "C" void kernel_launch(void* const* d_in, const int* in_sizes, int n_in,
                              void* d_out, int out_size)
{
    const float* x      = (const float*)d_in[0];   // [4,2048,1024]
    const float* W_qkv  = (const float*)d_in[1];   // [3072,1024]
    const float* W_proj = (const float*)d_in[2];   // [1024,1024]
    float* out = (float*)d_out;                    // [4,2048,1024]

    cudaFuncSetAttribute(gemm_tf32_kernel,
                         cudaFuncAttributeMaxDynamicSharedMemorySize,
                         GEMM_SMEM_BYTES);
    cudaFuncSetAttribute(attn_tf32_kernel,
                         cudaFuncAttributeMaxDynamicSharedMemorySize,
                         A_SMEM_BYTES);

    // 1) QKV GEMM + head-layout scatter (Q pre-scaled, tf32 bits)
    dim3 g1(3 * D_ / 256, M_ / 128);   // (12, 64)
    gemm_tf32_kernel<<<g1, 512, GEMM_SMEM_BYTES>>>(x, W_qkv, nullptr, M_, 3 * D_, D_, 0);

    // 2) Flash attention
    dim3 g2(T_ / 128, B_ * H_);        // (16, 64)
    attn_tf32_kernel<<<g2, 256, A_SMEM_BYTES>>>();

    // 3) Output projection
    dim3 g3(D_ / 256, M_ / 128);       // (4, 64)
    gemm_tf32_kernel<<<g3, 512, GEMM_SMEM_BYTES>>>(nullptr, W_proj, out, M_, D_, D_, 1);
}